// round 15
// baseline (speedup 1.0000x reference)
#include <cuda_runtime.h>

#define TPC 8    // tokens per CTA; grid = ceil(T/8) = 256
#define FMAX 128 // max frames per CTA: 8 tokens * dur<16 = 120

__device__ __forceinline__ float reluf(float x) { return x > 0.f ? x : 0.f; }

__device__ __forceinline__ float rerelu_f(float x) {
    const float offs[24] = {3.25f,3.75f,5.25f,5.75f,6.25f,6.75f,11.25f,11.75f,
                            15.25f,15.75f,20.25f,20.75f,23.25f,23.75f,35.25f,35.75f,
                            40.25f,40.75f,43.25f,43.75f,49.25f,49.75f,61.25f,61.75f};
    const float cfs[24]  = {4.f,-4.f,-4.f,4.f,4.f,-4.f,-2.f,2.f,2.f,-2.f,-2.f,2.f,
                            2.f,-2.f,-2.f,2.f,2.f,-2.f,-2.f,2.f,2.f,-2.f,-2.f,2.f};
    float s = 0.f;
#pragma unroll
    for (int k = 0; k < 24; k++)
        s = __fadd_rn(s, __fmul_rn(cfs[k], reluf(__fadd_rn(x, -offs[k]))));
    return s;
}

__device__ __forceinline__ float rerelu2_f(float x) {
    const float offs[6] = {1.25f,1.75f,2.25f,2.75f,3.25f,3.75f};
    const float cfs[6]  = {-2.f,2.f,2.f,-2.f,-2.f,2.f};
    float s = 1.f;
#pragma unroll
    for (int k = 0; k < 6; k++)
        s = __fadd_rn(s, __fmul_rn(cfs[k], reluf(__fadd_rn(x, -offs[k]))));
    return s;
}

__device__ __forceinline__ float rerelu3_f(float x) {
    float s = __fmul_rn(2.f, reluf(__fadd_rn(x, -1.25f)));
    s = __fadd_rn(s, __fmul_rn(-2.f, reluf(__fadd_rn(x, -1.75f))));
    return s;
}

__device__ __forceinline__ float rerelu4_f(float x) {
    float s = __fmul_rn(8.f, reluf(x));
    s = __fadd_rn(s, __fmul_rn(-8.f,  reluf(__fadd_rn(x, -1.f))));
    s = __fadd_rn(s, __fmul_rn(-0.3f, reluf(__fadd_rn(x, -1.f))));
    s = __fadd_rn(s, __fmul_rn(0.3f,  reluf(__fadd_rn(x, -21.f))));
    return s;
}

// 256-bit broadcast store (sm_100+): one instruction writes 8 floats.
__device__ __forceinline__ void st_v8_bcast(float* p, float v) {
    asm volatile("st.global.v8.f32 [%0], {%1,%1,%1,%1,%1,%1,%1,%1};"
                 :: "l"(p), "f"(v) : "memory");
}

// ---------------------------------------------------------------------------
// Single launch, grid = ceil(T/8) = 256, block = 512, 3 CTAs/SM forced via
// launch bounds (R13 structure + R14's occupancy cap; best of both).
//  Scan:    thread scans one int4 of durations (truncated to CTA window);
//           warp shuffle scan + warp-0 scan of 16 warp sums.
//  Params:  warp 0, tokens 8c-1 .. 8c+8.
//  Phase A: thread j computes mel for frame S0+j ONCE into smem.
//  Phase B: pure stores via st.global.v8.f32 (256-bit), ~2 iters/thread.
// fp op order identical to all prior rounds -> bit-identical output.
// ---------------------------------------------------------------------------
__global__ __launch_bounds__(512, 3) void fused_kernel(const int* __restrict__ dur,
                                                       const float* __restrict__ token,
                                                       float* __restrict__ out, int T) {
    __shared__ int   s_pre[TPC + 2];
    __shared__ int   s_dr[TPC + 2];
    __shared__ int   s_wsum[16];
    __shared__ int   s_wexcl[16];
    __shared__ int   s_si[TPC + 1];
    __shared__ int   s_di[TPC + 1];
    __shared__ float s_w[TPC + 1], s_sf[TPC + 1], s_ef[TPC + 1];
    __shared__ float s_mel[FMAX];

    int tid = threadIdx.x, lane = tid & 31, wid = tid >> 5;
    int c = blockIdx.x;
    int tfirst = TPC * c - 1;
    int tlast  = TPC * c + TPC;

    // Early token load + rerelu for the 10 window tokens (overlaps dur scan)
    float tokv = 0.f;
    if (wid == 0) {
        int tt = tfirst + lane;
        if (lane < TPC + 2 && tt >= 0 && tt < T)
            tokv = rerelu_f(token[tt]);
    }

    // Zero-init exactly the UNOWNED window cells (no race with owner writes)
    if (tid < TPC + 2) {
        int t = tfirst + tid;
        if (t < 0 || t >= T) { s_pre[tid] = 0; s_dr[tid] = 0; }
    }

    // ---- dur scan: one int4 per thread, truncated ----
    int g0 = 4 * tid;
    int4 v = make_int4(0, 0, 0, 0);
    if (g0 < T && g0 <= tlast) v = ((const int4*)dur)[tid];
    int e1 = v.x, e2 = e1 + v.y, e3 = e2 + v.z;
    int run = e3 + v.w;

    int incl = run;
#pragma unroll
    for (int o = 1; o < 32; o <<= 1) {
        int n = __shfl_up_sync(0xffffffffu, incl, o);
        if (lane >= o) incl += n;
    }
    int myExcl = incl - run;
    if (lane == 31) s_wsum[wid] = incl;

    {
        int r0 = g0 - tfirst;
        if (g0 < T) {
            if (r0 >= 0     && r0 < TPC + 2)                    { s_pre[r0]     = myExcl;      s_dr[r0]     = v.x; }
            if (r0 + 1 >= 0 && r0 + 1 < TPC + 2 && g0 + 1 < T) { s_pre[r0 + 1] = myExcl + e1; s_dr[r0 + 1] = v.y; }
            if (r0 + 2 >= 0 && r0 + 2 < TPC + 2 && g0 + 2 < T) { s_pre[r0 + 2] = myExcl + e2; s_dr[r0 + 2] = v.z; }
            if (r0 + 3 >= 0 && r0 + 3 < TPC + 2 && g0 + 3 < T) { s_pre[r0 + 3] = myExcl + e3; s_dr[r0 + 3] = v.w; }
        }
    }
    __syncthreads();

    // ---- warp 0: scan warp sums, then per-token params ----
    if (wid == 0) {
        int ws = (lane < 16) ? s_wsum[lane] : 0;
        int wincl = ws;
#pragma unroll
        for (int o = 1; o < 16; o <<= 1) {
            int n = __shfl_up_sync(0xffffffffu, wincl, o);
            if (lane >= o) wincl += n;
        }
        if (lane < 16) s_wexcl[lane] = wincl - ws;
        __syncwarp();

        float tok_next = __shfl_down_sync(0xffffffffu, tokv, 1);
        if (lane <= TPC) {
            int t = tfirst + lane;
            int start = 0, di = 0;
            if (t >= 0 && t < T) {
                di = s_dr[lane];
                start = s_pre[lane] + s_wexcl[t >> 7];
            }
            int dn = s_dr[lane + 1];
            float x  = __fadd_rn(tokv, tok_next);
            float s2 = rerelu2_f(x);
            float nd = __fadd_rn(__fmul_rn(s2, (float)dn), (float)di);
            float sf = (float)start;
            s_sf[lane] = sf;
            s_ef[lane] = __fadd_rn(sf, nd);
            float nt = rerelu3_f(tokv);
            s_w[lane]  = __fmul_rn(nt, nt);
            s_si[lane] = start;
            s_di[lane] = di;
        }
    }
    __syncthreads();

    int S0 = s_si[1];
    int F  = (s_si[TPC] + s_di[TPC]) - S0;

    // ---- Phase A: one thread per frame computes mel once ----
    if (tid < F) {
        int j = tid;
        int l = S0 + j;
        int r = 1;
#pragma unroll
        for (int k = 2; k <= TPC; k++) r += (l >= s_si[k]) ? 1 : 0;
        float lf = (float)l;
        float S = __fmul_rn(s_w[r], __fadd_rn(__fadd_rn(lf, -s_sf[r]), 1.f));
        if (tfirst + r > 0) {
            if (lf < s_ef[r - 1]) {
                float cc = __fmul_rn(s_w[r - 1],
                                     __fadd_rn(__fadd_rn(lf, -s_sf[r - 1]), 1.f));
                S = __fadd_rn(S, cc);
            }
        }
        s_mel[j] = rerelu4_f(S);
    }
    __syncthreads();

    // ---- Phase B: 256-bit broadcast stores ----
    // n8 = F * 16 (32B units per frame); <= 1920, ~2 iters/thread
    int n8 = F << 4;
    float* ob = out + (long long)S0 * 128;
    for (int i = tid; i < n8; i += 512) {
        float vv = s_mel[i >> 4];
        st_v8_bcast(ob + (size_t)i * 8, vv);
    }
}

extern "C" void kernel_launch(void* const* d_in, const int* in_sizes, int n_in,
                              void* d_out, int out_size) {
    const int*   dur   = (const int*)d_in[0];
    const float* token = (const float*)d_in[1];
    float* out = (float*)d_out;
    int T = in_sizes[0];
    if (T > 2048) T = 2048;  // scan covers up to 512 threads * 4 tokens

    int nblk = (T + TPC - 1) / TPC;
    fused_kernel<<<nblk, 512>>>(dur, token, out, T);
}

// round 17
// speedup vs baseline: 1.0669x; 1.0669x over previous
#include <cuda_runtime.h>

#define TPC 8    // tokens per CTA; grid = ceil(T/8) = 256
// max frames per CTA: 8 tokens * dur<16 = 120 < 16 warps * 8 frames

__device__ __forceinline__ float reluf(float x) { return x > 0.f ? x : 0.f; }

__device__ __forceinline__ float rerelu_f(float x) {
    const float offs[24] = {3.25f,3.75f,5.25f,5.75f,6.25f,6.75f,11.25f,11.75f,
                            15.25f,15.75f,20.25f,20.75f,23.25f,23.75f,35.25f,35.75f,
                            40.25f,40.75f,43.25f,43.75f,49.25f,49.75f,61.25f,61.75f};
    const float cfs[24]  = {4.f,-4.f,-4.f,4.f,4.f,-4.f,-2.f,2.f,2.f,-2.f,-2.f,2.f,
                            2.f,-2.f,-2.f,2.f,2.f,-2.f,-2.f,2.f,2.f,-2.f,-2.f,2.f};
    float s = 0.f;
#pragma unroll
    for (int k = 0; k < 24; k++)
        s = __fadd_rn(s, __fmul_rn(cfs[k], reluf(__fadd_rn(x, -offs[k]))));
    return s;
}

__device__ __forceinline__ float rerelu2_f(float x) {
    const float offs[6] = {1.25f,1.75f,2.25f,2.75f,3.25f,3.75f};
    const float cfs[6]  = {-2.f,2.f,2.f,-2.f,-2.f,2.f};
    float s = 1.f;
#pragma unroll
    for (int k = 0; k < 6; k++)
        s = __fadd_rn(s, __fmul_rn(cfs[k], reluf(__fadd_rn(x, -offs[k]))));
    return s;
}

__device__ __forceinline__ float rerelu3_f(float x) {
    float s = __fmul_rn(2.f, reluf(__fadd_rn(x, -1.25f)));
    s = __fadd_rn(s, __fmul_rn(-2.f, reluf(__fadd_rn(x, -1.75f))));
    return s;
}

__device__ __forceinline__ float rerelu4_f(float x) {
    float s = __fmul_rn(8.f, reluf(x));
    s = __fadd_rn(s, __fmul_rn(-8.f,  reluf(__fadd_rn(x, -1.f))));
    s = __fadd_rn(s, __fmul_rn(-0.3f, reluf(__fadd_rn(x, -1.f))));
    s = __fadd_rn(s, __fmul_rn(0.3f,  reluf(__fadd_rn(x, -21.f))));
    return s;
}

// 256-bit broadcast store (sm_100+): one instruction writes 8 floats.
__device__ __forceinline__ void st_v8_bcast(float* p, float v) {
    asm volatile("st.global.v8.f32 [%0], {%1,%1,%1,%1,%1,%1,%1,%1};"
                 :: "l"(p), "f"(v) : "memory");
}

// ---------------------------------------------------------------------------
// Single launch, grid = ceil(T/8) = 256, block = 512 (R13's measured optimum).
//  Scan:    thread scans one int4 of durations (truncated to CTA window);
//           warp shuffle scan + warp-0 scan of 16 warp sums.      [barrier 1]
//  Params:  warp 0, tokens 8c-1 .. 8c+8.                          [barrier 2]
//  Fill:    warp w owns frames [8w, 8w+8): lane j<8 computes mel once
//           in-register; 4 unrolled shfl-broadcast iterations store two
//           frames each (16 lanes x v8 per frame). NO third barrier,
//           no smem round trip; warps drain independently.
// fp op order identical to all prior rounds -> bit-identical output.
// ---------------------------------------------------------------------------
__global__ __launch_bounds__(512) void fused_kernel(const int* __restrict__ dur,
                                                    const float* __restrict__ token,
                                                    float* __restrict__ out, int T) {
    __shared__ int   s_pre[TPC + 2];
    __shared__ int   s_dr[TPC + 2];
    __shared__ int   s_wsum[16];
    __shared__ int   s_wexcl[16];
    __shared__ int   s_si[TPC + 1];
    __shared__ int   s_di[TPC + 1];
    __shared__ float s_w[TPC + 1], s_sf[TPC + 1], s_ef[TPC + 1];

    int tid = threadIdx.x, lane = tid & 31, wid = tid >> 5;
    int c = blockIdx.x;
    int tfirst = TPC * c - 1;
    int tlast  = TPC * c + TPC;

    // Early token load + rerelu for the 10 window tokens (overlaps dur scan)
    float tokv = 0.f;
    if (wid == 0) {
        int tt = tfirst + lane;
        if (lane < TPC + 2 && tt >= 0 && tt < T)
            tokv = rerelu_f(token[tt]);
    }

    // Zero-init exactly the UNOWNED window cells (no race with owner writes)
    if (tid < TPC + 2) {
        int t = tfirst + tid;
        if (t < 0 || t >= T) { s_pre[tid] = 0; s_dr[tid] = 0; }
    }

    // ---- dur scan: one int4 per thread, truncated ----
    int g0 = 4 * tid;
    int4 v = make_int4(0, 0, 0, 0);
    if (g0 < T && g0 <= tlast) v = ((const int4*)dur)[tid];
    int e1 = v.x, e2 = e1 + v.y, e3 = e2 + v.z;
    int run = e3 + v.w;

    int incl = run;
#pragma unroll
    for (int o = 1; o < 32; o <<= 1) {
        int n = __shfl_up_sync(0xffffffffu, incl, o);
        if (lane >= o) incl += n;
    }
    int myExcl = incl - run;
    if (lane == 31) s_wsum[wid] = incl;

    {
        int r0 = g0 - tfirst;
        if (g0 < T) {
            if (r0 >= 0     && r0 < TPC + 2)                    { s_pre[r0]     = myExcl;      s_dr[r0]     = v.x; }
            if (r0 + 1 >= 0 && r0 + 1 < TPC + 2 && g0 + 1 < T) { s_pre[r0 + 1] = myExcl + e1; s_dr[r0 + 1] = v.y; }
            if (r0 + 2 >= 0 && r0 + 2 < TPC + 2 && g0 + 2 < T) { s_pre[r0 + 2] = myExcl + e2; s_dr[r0 + 2] = v.z; }
            if (r0 + 3 >= 0 && r0 + 3 < TPC + 2 && g0 + 3 < T) { s_pre[r0 + 3] = myExcl + e3; s_dr[r0 + 3] = v.w; }
        }
    }
    __syncthreads();

    // ---- warp 0: scan warp sums, then per-token params ----
    if (wid == 0) {
        int ws = (lane < 16) ? s_wsum[lane] : 0;
        int wincl = ws;
#pragma unroll
        for (int o = 1; o < 16; o <<= 1) {
            int n = __shfl_up_sync(0xffffffffu, wincl, o);
            if (lane >= o) wincl += n;
        }
        if (lane < 16) s_wexcl[lane] = wincl - ws;
        __syncwarp();

        float tok_next = __shfl_down_sync(0xffffffffu, tokv, 1);
        if (lane <= TPC) {
            int t = tfirst + lane;
            int start = 0, di = 0;
            if (t >= 0 && t < T) {
                di = s_dr[lane];
                start = s_pre[lane] + s_wexcl[t >> 7];
            }
            int dn = s_dr[lane + 1];
            float x  = __fadd_rn(tokv, tok_next);
            float s2 = rerelu2_f(x);
            float nd = __fadd_rn(__fmul_rn(s2, (float)dn), (float)di);
            float sf = (float)start;
            s_sf[lane] = sf;
            s_ef[lane] = __fadd_rn(sf, nd);
            float nt = rerelu3_f(tokv);
            s_w[lane]  = __fmul_rn(nt, nt);
            s_si[lane] = start;
            s_di[lane] = di;
        }
    }
    __syncthreads();

    int S0 = s_si[1];
    int F  = (s_si[TPC] + s_di[TPC]) - S0;   // <= 120 < 128

    // ---- Fill: warp w owns frames [8w, 8w+8); mel in-register, no barrier ----
    int wbase = wid << 3;
    float mel = 0.f;
    if (lane < 8 && wbase + lane < F) {
        int l = S0 + wbase + lane;
        int r = 1;
#pragma unroll
        for (int k = 2; k <= TPC; k++) r += (l >= s_si[k]) ? 1 : 0;
        float lf = (float)l;
        float S = __fmul_rn(s_w[r], __fadd_rn(__fadd_rn(lf, -s_sf[r]), 1.f));
        if (tfirst + r > 0) {
            if (lf < s_ef[r - 1]) {
                float cc = __fmul_rn(s_w[r - 1],
                                     __fadd_rn(__fadd_rn(lf, -s_sf[r - 1]), 1.f));
                S = __fadd_rn(S, cc);
            }
        }
        mel = rerelu4_f(S);
    }

    // 4 paired iterations: lanes 0-15 store frame f0, lanes 16-31 frame f1.
    int half = lane >> 4;         // 0 or 1
    int unit = lane & 15;         // v8-unit within frame (16 x 32B = 512B)
#pragma unroll
    for (int p = 0; p < 4; p++) {
        int fj = wbase + 2 * p + half;
        float vv = __shfl_sync(0xffffffffu, mel, 2 * p + half);
        if (fj < F)
            st_v8_bcast(out + (size_t)(S0 + fj) * 128 + unit * 8, vv);
    }
}

extern "C" void kernel_launch(void* const* d_in, const int* in_sizes, int n_in,
                              void* d_out, int out_size) {
    const int*   dur   = (const int*)d_in[0];
    const float* token = (const float*)d_in[1];
    float* out = (float*)d_out;
    int T = in_sizes[0];
    if (T > 2048) T = 2048;  // scan covers up to 512 threads * 4 tokens

    int nblk = (T + TPC - 1) / TPC;
    fused_kernel<<<nblk, 512>>>(dur, token, out, T);
}